// round 17
// baseline (speedup 1.0000x reference)
#include <cuda_runtime.h>
#include <float.h>
#include <stdint.h>

// Fused MaxPool(2x2,s1,SAME) -> depthwise 3x3 binomial blur -> AvgPool(2x2,s2)
// == separable 4x4 stencil w=(1,3,3,1)/8 stride 2 over maxpool output y.
//
// R16: the converged R3 pipeline (double-buffered column pairs, 14-load 256B
// bursts, full compute block between burst and consume) with BOTH verified
// reg-neutral micro-levers stacked:
//   - packed f32x2 FMA chain (R15): 24 scalar FFMA/iter -> 12 packed ops
//   - 64-thread CTAs + __stcs streaming stores (R10): finer drain/backfill
//     quantum at the same 16 warps/SM; output lines don't evict live input.

#define NROWP  28
#define ROWSTR (112*64)     // float2 per x row
#define PXSTR  64           // float2 per pixel

// Packed weights: two identical fp32 halves of 0.125f / 0.375f.
#define W0P   0x3E0000003E000000ULL
#define W1P   0x3EC000003EC00000ULL

__device__ __forceinline__ float2 f2max(float2 a, float2 b) {
    return make_float2(fmaxf(a.x,b.x), fmaxf(a.y,b.y));
}
__device__ __forceinline__ uint64_t pk(float2 v) {      // free (reg aliasing)
    uint64_t r;
    asm("mov.b64 %0, {%1, %2};" : "=l"(r) : "f"(v.x), "f"(v.y));
    return r;
}
__device__ __forceinline__ uint64_t pmul(uint64_t a, uint64_t b) {
    uint64_t d;
    asm("mul.rn.f32x2 %0, %1, %2;" : "=l"(d) : "l"(a), "l"(b));
    return d;
}
__device__ __forceinline__ uint64_t pfma(uint64_t a, uint64_t b, uint64_t c) {
    uint64_t d;
    asm("fma.rn.f32x2 %0, %1, %2, %3;" : "=l"(d) : "l"(a), "l"(b), "l"(c));
    return d;
}

// Load 7 x-rows of one column. Rows 1..4 always in range; row 0 invalid only
// for the top strip, rows 5,6 invalid only for the bottom strip.
#define LOADCOL(dst, c, cOk) do {                                         \
    const float2* _p = base + (long long)(c) * PXSTR;                     \
    dst[0] = ((cOk) && okTop) ? __ldg(_p)              : NEG;             \
    dst[1] = (cOk) ? __ldg(_p + 1*ROWSTR) : NEG;                          \
    dst[2] = (cOk) ? __ldg(_p + 2*ROWSTR) : NEG;                          \
    dst[3] = (cOk) ? __ldg(_p + 3*ROWSTR) : NEG;                          \
    dst[4] = (cOk) ? __ldg(_p + 4*ROWSTR) : NEG;                          \
    dst[5] = ((cOk) && okBot) ? __ldg(_p + 5*ROWSTR) : NEG;               \
    dst[6] = ((cOk) && okBot) ? __ldg(_p + 6*ROWSTR) : NEG;               \
} while (0)

// Finalize one y column (TY literal after unroll): scalar maxes build yc,
// then the whole (1,3,3,1)/8 vertical + horizontal chain runs packed.
#define STEP(prevcm, curcm, TY) do {                                      \
    const bool _skip = ((TY)==0 && leftSkip) || ((TY)==29 && rightSkip);  \
    if (!_skip) {                                                         \
        float2 yc[6];                                                     \
        _Pragma("unroll")                                                 \
        for (int _k = 0; _k < 6; _k++) yc[_k] = f2max(prevcm[_k], curcm[_k]); \
        if (!okTop) yc[0] = ZERO;                                         \
        if (!okBot) yc[5] = ZERO;                                         \
        const int      _m  = (TY) >> 1;                                   \
        const uint64_t _wA = ((TY) & 1) ? W1P : W0P;                      \
        const uint64_t _wB = ((TY) & 1) ? W0P : W1P;                      \
        _Pragma("unroll")                                                 \
        for (int _rl = 0; _rl < 2; _rl++) {                               \
            uint64_t V = pmul(pk(yc[2*_rl + 0]), W0P);                    \
            V = pfma(pk(yc[2*_rl + 1]), W1P, V);                          \
            V = pfma(pk(yc[2*_rl + 2]), W1P, V);                          \
            V = pfma(pk(yc[2*_rl + 3]), W0P, V);                          \
            if (_m < 14) acc[_rl][_m & 1] = pfma(V, _wA, acc[_rl][_m & 1]); \
            if (_m >= 1) acc[_rl][(_m & 1) ^ 1] =                         \
                pfma(V, _wB, acc[_rl][(_m & 1) ^ 1]);                     \
        }                                                                 \
    }                                                                     \
} while (0)

__global__ void __launch_bounds__(64, 8)
mbp_kernel(const float2* __restrict__ x, uint64_t* __restrict__ out) {
    const int lane   = threadIdx.x;
    const int wid    = blockIdx.x * 2 + threadIdx.y;   // 7168 warp tasks
    const int chHalf = wid & 1;
    const int strip  = wid >> 1;                       // 3584 strips
    const int cj = strip & 3;                          // 4 col chunks of 14
    const int s2 = strip >> 2;
    const int ti = s2 % NROWP;                         // 28 row pairs
    const int b  = s2 / NROWP;

    const int oi0 = 2 * ti;
    const int oj0 = 14 * cj;
    const int xr0 = 4 * ti - 1;
    const int xc0 = 28 * cj - 1;

    const float2 NEG  = make_float2(-FLT_MAX, -FLT_MAX);
    const float2 ZERO = make_float2(0.f, 0.f);

    const bool okTop     = (ti != 0);
    const bool okBot     = (ti != NROWP - 1);
    const bool leftSkip  = (cj == 0);
    const bool rightSkip = (cj == 3);

    const float2* base = x + (size_t)b * 112 * 112 * 64 + chHalf * 32 + lane
                           + (long long)xr0 * ROWSTR;

    // Prime column xc0 -> cmPrev (column pair-maxes over x rows k,k+1)
    float2 cmPrev[6];
    {
        float2 xv[7];
        LOADCOL(xv, xc0, !leftSkip);                   // xc0 < 0 only if cj==0
#pragma unroll
        for (int k = 0; k < 6; k++) cmPrev[k] = f2max(xv[k], xv[k+1]);
    }

    uint64_t acc[2][2];                                // packed [row][col&1]
    acc[0][0]=0; acc[0][1]=0; acc[1][0]=0; acc[1][1]=0;

    uint64_t* ob = out + ((size_t)(b * 56 + oi0) * 56 + oj0) * 64
                       + chHalf * 32 + lane;

    // Double-buffered column pairs: buffer i&1 holds cols of iteration i.
    float2 xa[2][7], xb2[2][7];
    LOADCOL(xa[0],  xc0 + 1, true);
    LOADCOL(xb2[0], xc0 + 2, true);

#pragma unroll
    for (int i = 0; i < 15; i++) {
        const int cur = i & 1, nxt = cur ^ 1;
        if (i < 14) {                                  // 14-load burst, iter i+1
            const bool ok = (i < 13) || !rightSkip;    // only cols 112/113 bad
            LOADCOL(xa[nxt],  xc0 + 3 + 2*i, ok);
            LOADCOL(xb2[nxt], xc0 + 4 + 2*i, ok);
        }

        float2 cmA[6], cmB[6];
#pragma unroll
        for (int k = 0; k < 6; k++) {
            cmA[k] = f2max(xa[cur][k],  xa[cur][k+1]);
            cmB[k] = f2max(xb2[cur][k], xb2[cur][k+1]);
        }

        STEP(cmPrev, cmA, 2*i);                        // y col ty = 2i
        STEP(cmA,    cmB, 2*i + 1);                    // y col ty = 2i+1

        if (i >= 1) {                                  // out col i-1 complete
            const int wl = i - 1, slot = wl & 1;
#pragma unroll
            for (int rl = 0; rl < 2; rl++) {
                __stcs((unsigned long long*)&ob[((size_t)rl * 56 + wl) * 64],
                       (unsigned long long)acc[rl][slot]);
                acc[rl][slot] = 0;
            }
        }

#pragma unroll
        for (int k = 0; k < 6; k++) cmPrev[k] = cmB[k];
    }
}

extern "C" void kernel_launch(void* const* d_in, const int* in_sizes, int n_in,
                              void* d_out, int out_size) {
    const float2* x = (const float2*)d_in[0];   // (32,112,112,128) f32
    // d_in[1] = blur kernel, baked into (1,3,3,1)/8
    uint64_t* out = (uint64_t*)d_out;           // (32,56,56,128) f32

    // 3584 strips x 2 channel halves = 7168 warp tasks, 2 warps/CTA
    dim3 block(32, 2);
    dim3 grid(7168 / 2);                        // 3584 blocks
    mbp_kernel<<<grid, block>>>(x, out);
}